// round 6
// baseline (speedup 1.0000x reference)
#include <cuda_runtime.h>
#include <cstdint>

// Fused ConvTranspose3d(32->64,k5,s2,p2) + MaxPool2 + MaxPool3 + channel-sum.
// Pools compose into a 6x6x6 stride-6 max over conv output; bias folds after max.
//
// CTA = (n, d2, h2), 320 threads = 10 warps; warp = w2 window, lane = cout pair
// (f32x2, fma.rn.f32x2 = 2 MACs/inst). Full 6x6x6 window per warp (acc 36 u64).
// x patch duplicated-f32x2 in smem (200 KB) -> x reads are LDS.64 broadcasts.
// Weights: prep kernel lays them out per (cin,kh) as contiguous 800-u64 blocks;
// a cp.async 4-deep ring (4 x 6.4 KB) stages one block per (oh,cin,khi) stage,
// 3 in flight. In the mainloop weights are conflict-free LDS.64 into a 25-reg
// cache reused for 195 FFMA2 (7.8 MACs per weight fetch -> L1tex no longer binds).

#define CIN 32
#define COUT 64
#define DI 16
#define HI 32
#define WI 32
#define NTH 320
#define XS_ELEMS 25600                   // 32cin * 5ad * 5ah * 32slots (u64)
#define WSTG_U64 800                     // 25 taps * 32 lanes per stage
#define NBUF 4
#define SMEM_BYTES (XS_ELEMS * 8 + NBUF * WSTG_U64 * 8)   // 204800 + 25600 = 230400

typedef unsigned long long u64;

// [( (cin*5 + kh)*25 + kd*5 + kw )*32 + lane] ; one (cin,kh) block = 800 contiguous u64
__device__ u64 g_wp2[CIN * 5 * 25 * 32];

__global__ void prep_kernel(const float* __restrict__ w) {
    int idx = blockIdx.x * blockDim.x + threadIdx.x;
    if (idx >= CIN * 5 * 25 * 32) return;
    int lane = idx & 31;
    int t = idx >> 5;
    int cin = t / 125;
    int r = t % 125;
    int kh = r / 25;
    int kd = (r % 25) / 5;
    int kw = r % 5;
    int tap = (kd * 5 + kh) * 5 + kw;      // torch tap order (kd,kh,kw)
    unsigned int a = __float_as_uint(w[(cin * COUT + 2 * lane) * 125 + tap]);
    unsigned int b = __float_as_uint(w[(cin * COUT + 2 * lane + 1) * 125 + tap]);
    g_wp2[idx] = ((u64)b << 32) | (u64)a;
}

__device__ __forceinline__ u64 ffma2(u64 a, u64 b, u64 c) {
    u64 d;
    asm("fma.rn.f32x2 %0, %1, %2, %3;" : "=l"(d) : "l"(a), "l"(b), "l"(c));
    return d;
}
__device__ __forceinline__ void unpack2(u64 v, float& lo, float& hi) {
    asm("mov.b64 {%0, %1}, %2;" : "=f"(lo), "=f"(hi) : "l"(v));
}
__device__ __forceinline__ void cp8(unsigned int smem_addr, const u64* g) {
    asm volatile("cp.async.ca.shared.global [%0], [%1], 8;" :: "r"(smem_addr), "l"(g));
}
__device__ __forceinline__ void cp_commit() {
    asm volatile("cp.async.commit_group;");
}
template <int N>
__device__ __forceinline__ void cp_wait() {
    asm volatile("cp.async.wait_group %0;" :: "n"(N));
}

// One (cin,kh) stage: weights from staged smem block, x from broadcast smem.
__device__ __forceinline__ void accum_stage(u64 acc[36],
                                            const u64* __restrict__ xsu,
                                            const u64* __restrict__ wst,
                                            int oh, int kh, int cin,
                                            int w2, int lane) {
    int ah = ((oh + 2 - kh) >> 1) + 1;          // in [0,4]
    u64 wreg[5][5];
#pragma unroll
    for (int kd = 0; kd < 5; kd++)
#pragma unroll
        for (int kw = 0; kw < 5; kw++)
            wreg[kd][kw] = wst[(kd * 5 + kw) * 32 + lane];   // LDS.64, conflict-free

    const u64* xb = xsu + (cin * 25 + ah) * 32 + 3 * w2;
#pragma unroll
    for (int a = 0; a < 5; a++) {
        u64 xp[5];
#pragma unroll
        for (int j = 0; j < 5; j++) xp[j] = xb[a * 160 + j];  // LDS.64 broadcast
#pragma unroll
        for (int kd = 0; kd < 5; kd++) {
            int odl = 2 * a + kd - 4;            // compile-time after unroll
            if (odl < 0 || odl > 5) continue;
#pragma unroll
            for (int kw = 0; kw < 5; kw++) {
                int p = kw & 1;
                int jb = 2 - (kw >> 1);
#pragma unroll
                for (int t3 = 0; t3 < 3; t3++) {
                    int ow = p + 2 * t3;
                    acc[odl * 6 + ow] = ffma2(wreg[kd][kw], xp[jb + t3], acc[odl * 6 + ow]);
                }
            }
        }
    }
}

extern __shared__ u64 smem_dyn[];

struct Cursor { int oh, cin, khi; };

__device__ __forceinline__ void issue_stage(const Cursor& c, int buf,
                                            unsigned int wbase_sa, int tid) {
    if (c.oh < 6) {
        int par = c.oh & 1;
        int kh = par + 2 * c.khi;
        const u64* src = g_wp2 + (c.cin * 5 + kh) * WSTG_U64;
        unsigned int dst = wbase_sa + buf * (WSTG_U64 * 8);
        cp8(dst + tid * 8, src + tid);
        cp8(dst + (tid + 320) * 8, src + tid + 320);
        if (tid < 160) cp8(dst + (tid + 640) * 8, src + tid + 640);
    }
    cp_commit();                                  // empty group past the end is legal
}

__device__ __forceinline__ void advance(Cursor& c) {
    int nkh = (c.oh & 1) ? 2 : 3;
    if (++c.khi == nkh) {
        c.khi = 0;
        if (++c.cin == CIN) { c.cin = 0; c.oh++; }
    }
}

__global__ void __launch_bounds__(NTH, 1)
fused_kernel(const float* __restrict__ x, const float* __restrict__ bias,
             float* __restrict__ out) {
    u64* xsu = smem_dyn;
    u64* wring = smem_dyn + XS_ELEMS;
    unsigned int wbase_sa = (unsigned int)__cvta_generic_to_shared(wring);

    int blk = blockIdx.x;
    int h2 = blk % 10;
    int d2 = (blk / 10) % 5;
    int n = blk / 50;
    int tid = threadIdx.x;

    // ---- prologue: prefetch weight stages 0..2 while x patch loads ----
    Cursor pc{0, 0, 0};
    issue_stage(pc, 0, wbase_sa, tid); advance(pc);
    issue_stage(pc, 1, wbase_sa, tid); advance(pc);
    issue_stage(pc, 2, wbase_sa, tid); advance(pc);

    // ---- load input patch: cin x (id0..id0+4) x (ih0..ih0+4) x (iw=-1..30) ----
    int id0 = 3 * d2 - 1, ih0 = 3 * h2 - 1;
    const float* xbase = x + (size_t)n * CIN * DI * HI * WI;
    for (int i = tid; i < XS_ELEMS; i += NTH) {
        int slot = i & 31;               // iw + 1
        int ah = (i >> 5) % 5;
        int rest = i / 160;
        int ad = rest % 5;
        int cin = rest / 5;
        int iw = slot - 1, id = id0 + ad, ih = ih0 + ah;
        float v = 0.f;
        if (iw >= 0 && id >= 0 && ih >= 0)   // upper bounds always in range for used windows
            v = xbase[((cin * DI + id) * HI + ih) * WI + iw];
        unsigned int u = __float_as_uint(v);
        xsu[i] = ((u64)u << 32) | (u64)u;    // duplicate into both f32x2 halves
    }

    int w2 = tid >> 5;                   // warp id = output w2 window
    int lane = tid & 31;                 // cout pair (2*lane, 2*lane+1)
    float m0 = -3.4e38f, m1 = -3.4e38f;
    int s = 0;                           // stage counter

#pragma unroll 1
    for (int oh = 0; oh < 6; oh++) {
        int par = oh & 1;
        int nkh = par ? 2 : 3;
        u64 acc[36];
#pragma unroll
        for (int i = 0; i < 36; i++) acc[i] = 0ull;

#pragma unroll 1
        for (int cin = 0; cin < CIN; cin++) {
#pragma unroll 1
            for (int khi = 0; khi < nkh; khi++) {
                cp_wait<2>();            // stage s landed (own groups)
                __syncthreads();         // visibility + all warps done with buf (s-1)%4
                issue_stage(pc, (s + 3) & 3, wbase_sa, tid);  // refill freed buffer
                advance(pc);
                int kh = par + 2 * khi;
                accum_stage(acc, xsu, wring + (s & 3) * WSTG_U64, oh, kh, cin, w2, lane);
                s++;
            }
        }

        // fold this oh-plane (6 od x 6 ow) into the running per-channel max
#pragma unroll
        for (int i = 0; i < 36; i++) {
            float lo, hi;
            unpack2(acc[i], lo, hi);
            m0 = fmaxf(m0, lo);
            m1 = fmaxf(m1, hi);
        }
    }

    float b0 = bias[2 * lane], b1 = bias[2 * lane + 1];
    float sm = (m0 + b0) + (m1 + b1);    // bias after max; sum lane's 2 couts
#pragma unroll
    for (int off = 16; off; off >>= 1) sm += __shfl_xor_sync(0xffffffffu, sm, off);
    if (lane == 0) out[((n * 5 + d2) * 10 + h2) * 10 + w2] = sm;
}

extern "C" void kernel_launch(void* const* d_in, const int* in_sizes, int n_in,
                              void* d_out, int out_size) {
    const float* x = (const float*)d_in[0];
    const float* w = (const float*)d_in[1];
    const float* b = (const float*)d_in[2];
    float* out = (float*)d_out;

    static int configured = 0;
    if (!configured) {
        cudaFuncSetAttribute(fused_kernel, cudaFuncAttributeMaxDynamicSharedMemorySize,
                             SMEM_BYTES);
        configured = 1;
    }

    prep_kernel<<<(CIN * 5 * 25 * 32 + 255) / 256, 256>>>(w);
    fused_kernel<<<16 * 5 * 10, NTH, SMEM_BYTES>>>(x, b, out);
}